// round 8
// baseline (speedup 1.0000x reference)
#include <cuda_runtime.h>
#include <cuda_bf16.h>

// Problem constants (fixed shapes)
#define S_NUM   16
#define T_MAX   11
#define ROWS    64
#define HID     768
#define SEQ     512

#define BERT_ELEMS   (S_NUM * SEQ * HID)        // 6291456
#define MTL_OFF      BERT_ELEMS
#define MTL_ELEMS    (S_NUM * HID)              // 12288
#define PROBS_OFF    (MTL_OFF + MTL_ELEMS)

#define H4           (HID / 4)                  // 192
#define E4_PER_SLICE (SEQ * H4)                 // 98304 float4 per slice
#define MTL_E4       (MTL_ELEMS / 4)            // 3072

#define BX_BERT      192                        // bert blocks per slice (256thr x 2 f4 = 512 e)

// Scratch (no device mallocs allowed)
__device__ float g_w[ROWS];
__device__ volatile int g_flag;                 // 0 -> weights not ready

// ---------------------------------------------------------------------------
__device__ __forceinline__ void wait_flag()
{
    if (threadIdx.x == 0) {
        while (g_flag == 0) __nanosleep(64);
        __threadfence();                         // acquire: order g_w loads after flag
    }
    __syncthreads();
}

// ---------------------------------------------------------------------------
// Fused kernel. Grid (BX_BERT+1, S_NUM), block 256.
//  bx <  192          : bert weighted segment-sum for slice by (2 float4/thr)
//  bx == 192, by == 0 : compute dot products + softmax, publish g_w, set flag,
//                       write probs output
//  bx == 192, by >= 1 : mtl segment-sum (15 blocks cover 3072 float4)
// ---------------------------------------------------------------------------
__global__ void __launch_bounds__(256)
fused_kernel(const float4* __restrict__ bert,   // [64, E4_PER_SLICE]
             const float4* __restrict__ hist4,  // [64, H4]
             const float4* __restrict__ mtl4,   // [64, H4]
             const float4* __restrict__ W4,     // [H4]
             const float*  __restrict__ b,      // [1]
             const int*    __restrict__ smask,  // [64]
             float*        __restrict__ out)
{
    const int tid = threadIdx.x;
    const int bx  = blockIdx.x;
    const int by  = blockIdx.y;

    __shared__ int s_m[S_NUM];
    if (tid < S_NUM) s_m[tid] = __ldg(smask + tid);
    __syncthreads();

    if (bx < BX_BERT) {
        // ---- bert streaming block, slice = by ----
        const int s = by;
        int off = 0;
        for (int i = 0; i < s; i++) off += s_m[i];   // shared reads, cheap
        const int n = s_m[s];

        const int e0 = bx * 512 + tid;
        const int e1 = e0 + 256;
        float4* out4 = (float4*)out + (size_t)s * E4_PER_SLICE;

        if (n == 4) {
            // fast path: prefetch all 8 loads BEFORE waiting on weights
            const float4* r0 = bert + (size_t)(off + 0) * E4_PER_SLICE;
            const float4* r1 = bert + (size_t)(off + 1) * E4_PER_SLICE;
            const float4* r2 = bert + (size_t)(off + 2) * E4_PER_SLICE;
            const float4* r3 = bert + (size_t)(off + 3) * E4_PER_SLICE;
            float4 a0 = __ldcs(r0 + e0), a1 = __ldcs(r1 + e0);
            float4 a2 = __ldcs(r2 + e0), a3 = __ldcs(r3 + e0);
            float4 c0 = __ldcs(r0 + e1), c1 = __ldcs(r1 + e1);
            float4 c2 = __ldcs(r2 + e1), c3 = __ldcs(r3 + e1);

            wait_flag();

            float w0 = __ldcg(&g_w[off + 0]);
            float w1 = __ldcg(&g_w[off + 1]);
            float w2 = __ldcg(&g_w[off + 2]);
            float w3 = __ldcg(&g_w[off + 3]);

            float4 acc0, acc1;
            acc0.x = w0*a0.x + w1*a1.x + w2*a2.x + w3*a3.x;
            acc0.y = w0*a0.y + w1*a1.y + w2*a2.y + w3*a3.y;
            acc0.z = w0*a0.z + w1*a1.z + w2*a2.z + w3*a3.z;
            acc0.w = w0*a0.w + w1*a1.w + w2*a2.w + w3*a3.w;
            acc1.x = w0*c0.x + w1*c1.x + w2*c2.x + w3*c3.x;
            acc1.y = w0*c0.y + w1*c1.y + w2*c2.y + w3*c3.y;
            acc1.z = w0*c0.z + w1*c1.z + w2*c2.z + w3*c3.z;
            acc1.w = w0*c0.w + w1*c1.w + w2*c2.w + w3*c3.w;
            __stcs(out4 + e0, acc0);
            __stcs(out4 + e1, acc1);
        } else {
            // generic path (any n 1..T_MAX)
            wait_flag();
            float4 acc0 = make_float4(0.f, 0.f, 0.f, 0.f);
            float4 acc1 = make_float4(0.f, 0.f, 0.f, 0.f);
            for (int j = 0; j < n; j++) {
                float w = __ldcg(&g_w[off + j]);
                const float4* r = bert + (size_t)(off + j) * E4_PER_SLICE;
                float4 v0 = __ldcs(r + e0);
                float4 v1 = __ldcs(r + e1);
                acc0.x += w*v0.x; acc0.y += w*v0.y; acc0.z += w*v0.z; acc0.w += w*v0.w;
                acc1.x += w*v1.x; acc1.y += w*v1.y; acc1.z += w*v1.z; acc1.w += w*v1.w;
            }
            __stcs(out4 + e0, acc0);
            __stcs(out4 + e1, acc1);
        }
        return;
    }

    if (by == 0) {
        // ---- weights block: 64 dot products, softmax, publish ----
        __shared__ float s_d[ROWS];
        const int lane = tid & 31;
        const int wid  = tid >> 5;                  // 0..7, warp handles 8 rows
        const float bias = b[0];

        for (int rr = 0; rr < 8; rr++) {
            int row = wid * 8 + rr;
            const float4* h = hist4 + row * H4;
            float acc = 0.f;
            #pragma unroll
            for (int k = lane; k < H4; k += 32) {
                float4 w = W4[k];
                float4 a = h[k];
                acc += a.x*w.x + a.y*w.y + a.z*w.z + a.w*w.w;
            }
            #pragma unroll
            for (int d = 16; d > 0; d >>= 1)
                acc += __shfl_xor_sync(0xffffffffu, acc, d);
            if (lane == 0) s_d[row] = acc + bias;
        }
        __syncthreads();

        __shared__ float s_probs[S_NUM * T_MAX];
        if (tid < S_NUM) {
            int s = tid;
            int off = 0;
            for (int i = 0; i < s; i++) off += s_m[i];
            int n   = s_m[s];
            int pad = T_MAX - n;
            float e[T_MAX];
            float denom = 0.f;
            #pragma unroll
            for (int t = 0; t < T_MAX; t++) {
                float v = (t >= pad) ? expf(s_d[off + t - pad]) : 0.f;
                e[t] = v;
                denom += v;
            }
            float inv = 1.f / denom;
            #pragma unroll
            for (int t = 0; t < T_MAX; t++)
                s_probs[s * T_MAX + t] = e[t] * inv;
            for (int j = 0; j < n; j++)
                g_w[off + j] = e[pad + j] * inv;
            __threadfence();                     // release: g_w before flag
        }
        __syncthreads();
        if (tid == 0) g_flag = 1;

        // probs output
        if (tid < S_NUM * T_MAX)
            out[PROBS_OFF + tid] = s_probs[tid];
        return;
    }

    // ---- mtl blocks: by in [1,15], 15*256 >= 3072 outputs ----
    {
        int idx = (by - 1) * 256 + tid;
        if (idx < MTL_E4) {
            int s = idx / H4;
            int e = idx - s * H4;
            int off = 0;
            for (int i = 0; i < s; i++) off += s_m[i];
            int n = s_m[s];

            wait_flag();

            float4 acc = make_float4(0.f, 0.f, 0.f, 0.f);
            for (int j = 0; j < n; j++) {
                float w  = __ldcg(&g_w[off + j]);
                float4 v = __ldg(mtl4 + (off + j) * H4 + e);
                acc.x += w*v.x; acc.y += w*v.y; acc.z += w*v.z; acc.w += w*v.w;
            }
            ((float4*)(out + MTL_OFF))[idx] = acc;
        } else {
            wait_flag();                         // keep block-uniform barrier use
        }
    }
}

// Reset the flag for the next graph replay (stream-ordered after fused_kernel).
__global__ void reset_kernel() { g_flag = 0; }

extern "C" void kernel_launch(void* const* d_in, const int* in_sizes, int n_in,
                              void* d_out, int out_size)
{
    const float* bert  = (const float*)d_in[0];   // [64, 512, 768]
    const float* hist  = (const float*)d_in[1];   // [64, 768]
    const float* mtl   = (const float*)d_in[2];   // [64, 768]
    const float* W     = (const float*)d_in[3];   // [1, 768]
    const float* b     = (const float*)d_in[4];   // [1]
    const int*   smask = (const int*)d_in[5];     // [64]
    float* out = (float*)d_out;

    dim3 grid(BX_BERT + 1, S_NUM);
    fused_kernel<<<grid, 256>>>((const float4*)bert, (const float4*)hist,
                                (const float4*)mtl, (const float4*)W,
                                b, smask, out);
    reset_kernel<<<1, 1>>>();
}

// round 9
// speedup vs baseline: 1.7334x; 1.7334x over previous
#include <cuda_runtime.h>
#include <cuda_bf16.h>

// Problem constants (fixed shapes)
#define S_NUM   16
#define T_MAX   11
#define ROWS    64
#define HID     768
#define SEQ     512

#define BERT_ELEMS   (S_NUM * SEQ * HID)        // 6291456
#define MTL_OFF      BERT_ELEMS
#define MTL_ELEMS    (S_NUM * HID)              // 12288
#define PROBS_OFF    (MTL_OFF + MTL_ELEMS)

#define H4           (HID / 4)                  // 192
#define E4_PER_SLICE (SEQ * H4)                 // 98304 float4 per slice
#define MTL4_PER_S   (HID / 4)                  // 192 float4 of mtl output per slice

#define BX_BERT      384                        // 384 blocks * 256 thr = 98304 f4/slice

// Scratch (no device mallocs allowed)
__device__ float g_w[ROWS];

// ---------------------------------------------------------------------------
// Kernel A: 64 dot products, softmax, publish g_w, trigger dependents, probs.
// One block, 1024 threads.
// ---------------------------------------------------------------------------
__global__ void __launch_bounds__(1024, 1)
small_kernel(const float4* __restrict__ hist4,  // [ROWS, H4]
             const float4* __restrict__ W4,     // [H4]
             const float*  __restrict__ b,      // [1]
             const int*    __restrict__ smask,  // [64]
             float*        __restrict__ out)
{
    __shared__ float s_d[ROWS];
    __shared__ int   s_m[S_NUM];
    __shared__ float s_probs[S_NUM * T_MAX];

    const int tid  = threadIdx.x;
    const int lane = tid & 31;
    const int wid  = tid >> 5;                  // 0..31, warp handles 2 rows

    if (tid < S_NUM) s_m[tid] = __ldg(smask + tid);

    // dot products: warp w -> rows 2w, 2w+1
    const float bias = b[0];
    {
        float acc0 = 0.f, acc1 = 0.f;
        const float4* h0 = hist4 + (2 * wid + 0) * H4;
        const float4* h1 = hist4 + (2 * wid + 1) * H4;
        #pragma unroll
        for (int k = lane; k < H4; k += 32) {
            float4 w = W4[k];
            float4 a = h0[k];
            float4 c = h1[k];
            acc0 += a.x*w.x + a.y*w.y + a.z*w.z + a.w*w.w;
            acc1 += c.x*w.x + c.y*w.y + c.z*w.z + c.w*w.w;
        }
        #pragma unroll
        for (int d = 16; d > 0; d >>= 1) {
            acc0 += __shfl_xor_sync(0xffffffffu, acc0, d);
            acc1 += __shfl_xor_sync(0xffffffffu, acc1, d);
        }
        if (lane == 0) {
            s_d[2 * wid + 0] = acc0 + bias;
            s_d[2 * wid + 1] = acc1 + bias;
        }
    }
    __syncthreads();

    // softmax per slice -> g_w (16 threads)
    if (tid < S_NUM) {
        int s = tid;
        int off = 0;
        for (int i = 0; i < s; i++) off += s_m[i];
        int n   = s_m[s];
        int pad = T_MAX - n;
        float e[T_MAX];
        float denom = 0.f;
        #pragma unroll
        for (int t = 0; t < T_MAX; t++) {
            float v = (t >= pad) ? expf(s_d[off + t - pad]) : 0.f;
            e[t] = v;
            denom += v;
        }
        float inv = 1.f / denom;
        #pragma unroll
        for (int t = 0; t < T_MAX; t++)
            s_probs[s * T_MAX + t] = e[t] * inv;
        for (int j = 0; j < n; j++)
            g_w[off + j] = e[pad + j] * inv;
    }
    __threadfence();        // make g_w globally visible before trigger
    __syncthreads();

    // Allow the dependent grid to proceed (its GridDependencySynchronize
    // waits for this). g_w is published; only probs writes remain.
    cudaTriggerProgrammaticLaunchCompletion();

    if (tid < S_NUM * T_MAX)
        out[PROBS_OFF + tid] = s_probs[tid];
}

// ---------------------------------------------------------------------------
// Kernel B (PDL secondary). Grid (BX_BERT+1, S_NUM), block 256.
//  bx < 384 : bert weighted segment-sum, slice by, 1 float4/thread.
//             Loads issued BEFORE the grid-dependency wait.
//  bx == 384: mtl segment-sum for slice by (192 float4).
// ---------------------------------------------------------------------------
__global__ void __launch_bounds__(256)
big_kernel(const float4* __restrict__ bert,     // [64, E4_PER_SLICE]
           const float4* __restrict__ mtl4,     // [64, H4]
           const int*    __restrict__ smask,    // [64]
           float*        __restrict__ out)
{
    const int tid = threadIdx.x;
    const int bx  = blockIdx.x;
    const int s   = blockIdx.y;

    __shared__ int s_m[S_NUM];
    if (tid < S_NUM) s_m[tid] = __ldg(smask + tid);
    __syncthreads();

    int off = 0;
    for (int i = 0; i < s; i++) off += s_m[i];
    const int n = s_m[s];

    if (bx < BX_BERT) {
        const int e = bx * 256 + tid;
        float4* out4 = (float4*)out + (size_t)s * E4_PER_SLICE;

        if (n == 4) {
            // issue all 4 loads before waiting on the primary grid
            float4 a0 = __ldcs(bert + (size_t)(off + 0) * E4_PER_SLICE + e);
            float4 a1 = __ldcs(bert + (size_t)(off + 1) * E4_PER_SLICE + e);
            float4 a2 = __ldcs(bert + (size_t)(off + 2) * E4_PER_SLICE + e);
            float4 a3 = __ldcs(bert + (size_t)(off + 3) * E4_PER_SLICE + e);

            cudaGridDependencySynchronize();

            float w0 = g_w[off + 0];
            float w1 = g_w[off + 1];
            float w2 = g_w[off + 2];
            float w3 = g_w[off + 3];

            float4 acc;
            acc.x = w0*a0.x + w1*a1.x + w2*a2.x + w3*a3.x;
            acc.y = w0*a0.y + w1*a1.y + w2*a2.y + w3*a3.y;
            acc.z = w0*a0.z + w1*a1.z + w2*a2.z + w3*a3.z;
            acc.w = w0*a0.w + w1*a1.w + w2*a2.w + w3*a3.w;
            __stcs(out4 + e, acc);
        } else if (n == 1) {
            float4 a0 = __ldcs(bert + (size_t)off * E4_PER_SLICE + e);
            cudaGridDependencySynchronize();
            float w0 = g_w[off];
            float4 acc;
            acc.x = w0*a0.x; acc.y = w0*a0.y; acc.z = w0*a0.z; acc.w = w0*a0.w;
            __stcs(out4 + e, acc);
        } else {
            cudaGridDependencySynchronize();
            float4 acc = make_float4(0.f, 0.f, 0.f, 0.f);
            for (int j = 0; j < n; j++) {
                float w  = g_w[off + j];
                float4 v = __ldcs(bert + (size_t)(off + j) * E4_PER_SLICE + e);
                acc.x += w*v.x; acc.y += w*v.y; acc.z += w*v.z; acc.w += w*v.w;
            }
            __stcs(out4 + e, acc);
        }
    } else {
        // mtl block for slice s: 192 float4 outputs
        cudaGridDependencySynchronize();
        if (tid < MTL4_PER_S) {
            float4 acc = make_float4(0.f, 0.f, 0.f, 0.f);
            for (int j = 0; j < n; j++) {
                float w  = g_w[off + j];
                float4 v = __ldg(mtl4 + (off + j) * H4 + tid);
                acc.x += w*v.x; acc.y += w*v.y; acc.z += w*v.z; acc.w += w*v.w;
            }
            ((float4*)(out + MTL_OFF))[s * MTL4_PER_S + tid] = acc;
        }
    }
}

extern "C" void kernel_launch(void* const* d_in, const int* in_sizes, int n_in,
                              void* d_out, int out_size)
{
    const float* bert  = (const float*)d_in[0];   // [64, 512, 768]
    const float* hist  = (const float*)d_in[1];   // [64, 768]
    const float* mtl   = (const float*)d_in[2];   // [64, 768]
    const float* W     = (const float*)d_in[3];   // [1, 768]
    const float* b     = (const float*)d_in[4];   // [1]
    const int*   smask = (const int*)d_in[5];     // [64]
    float* out = (float*)d_out;

    small_kernel<<<1, 1024>>>((const float4*)hist, (const float4*)W, b, smask, out);

    // Secondary grid with programmatic dependent launch: it may begin while
    // small_kernel is still running; cudaGridDependencySynchronize() inside
    // provides the ordering on g_w.
    cudaLaunchConfig_t cfg = {};
    cfg.gridDim  = dim3(BX_BERT + 1, S_NUM, 1);
    cfg.blockDim = dim3(256, 1, 1);
    cfg.dynamicSmemBytes = 0;
    cfg.stream = 0;
    cudaLaunchAttribute attr[1];
    attr[0].id = cudaLaunchAttributeProgrammaticStreamSerialization;
    attr[0].val.programmaticStreamSerializationAllowed = 1;
    cfg.attrs = attr;
    cfg.numAttrs = 1;

    const float4* bert4 = (const float4*)bert;
    const float4* mtl4  = (const float4*)mtl;
    cudaLaunchKernelEx(&cfg, big_kernel, bert4, mtl4, smask, out);
}